// round 1
// baseline (speedup 1.0000x reference)
#include <cuda_runtime.h>

// ---------------- problem constants ----------------
#define N_PTS 32768
#define TILE 1024
#define T_TILES (N_PTS / TILE)                    // 32
#define NPAIR_BLOCKS (T_TILES * (T_TILES + 1) / 2) // 528
#define PAIR_THREADS 256
#define IB 4                                       // i-points per thread (256*4 = 1024 = TILE)
#define SCALE 3.5f

// ---------------- device scratch (no allocs allowed) ----------------
// g_pts[i] = { x*s, y*s, 1+sq, sq }
__device__ float4 g_pts[N_PTS];
// 0: Z_full (incl. diagonal), 1: sum p*log(1+d2), 2: sum p, 3: sum p*log(p)
__device__ double g_acc[4];

__device__ __forceinline__ float frcp(float x) {
    float r;
    asm("rcp.approx.ftz.f32 %0, %1;" : "=f"(r) : "f"(x));
    return r;
}

// ---------------- prep: scale points, precompute norms, zero accumulators ----
__global__ void k_prep(const float2* __restrict__ emb, int n) {
    int i = blockIdx.x * blockDim.x + threadIdx.x;
    if (i == 0) {
        g_acc[0] = 0.0; g_acc[1] = 0.0; g_acc[2] = 0.0; g_acc[3] = 0.0;
    }
    if (i < n) {
        float2 e = emb[i];
        float x = e.x * SCALE;
        float y = e.y * SCALE;
        float sq = fmaf(x, x, y * y);
        g_pts[i] = make_float4(x, y, 1.0f + sq, sq);
    }
}

// ---------------- pairwise partition sum over tile upper triangle -----------
__global__ void __launch_bounds__(PAIR_THREADS) k_pair() {
    __shared__ float4 sj[TILE];

    int t = blockIdx.x;
    // invert lower-triangular linear index: t = r*(r+1)/2 + c, c <= r
    int r = (int)((sqrtf(8.0f * (float)t + 1.0f) - 1.0f) * 0.5f);
    while ((r + 1) * (r + 2) / 2 <= t) r++;
    while (r * (r + 1) / 2 > t) r--;
    int c = t - r * (r + 1) / 2;
    int bi = c, bj = r;  // bi <= bj

    int jbase = bj * TILE;
    int ibase = bi * TILE;

    for (int k = threadIdx.x; k < TILE; k += PAIR_THREADS)
        sj[k] = g_pts[jbase + k];
    __syncthreads();

    float m[IB], nn[IB], s[IB], acc[IB];
    int i0 = ibase + threadIdx.x * IB;
#pragma unroll
    for (int k = 0; k < IB; k++) {
        float4 P = g_pts[i0 + k];
        m[k]  = -2.0f * P.x;
        nn[k] = -2.0f * P.y;
        s[k]  = P.w;      // sq_i
        acc[k] = 0.0f;
    }

#pragma unroll 4
    for (int j = 0; j < TILE; j++) {
        float4 J = sj[j];  // J.x, J.y, J.z = 1+sq_j
#pragma unroll
        for (int k = 0; k < IB; k++) {
            float t0 = fmaf(m[k],  J.x, J.z);   // 1+sq_j - 2 x_i x_j
            float t1 = fmaf(nn[k], J.y, s[k]);  // sq_i   - 2 y_i y_j
            acc[k] += frcp(t0 + t1);            // 1/(1+d2)
        }
    }

    double dsum = ((double)acc[0] + (double)acc[1]) +
                  ((double)acc[2] + (double)acc[3]);
    if (bi != bj) dsum *= 2.0;  // off-diagonal tiles counted twice by symmetry

#pragma unroll
    for (int o = 16; o > 0; o >>= 1)
        dsum += __shfl_down_sync(0xffffffffu, dsum, o);
    if ((threadIdx.x & 31) == 0)
        atomicAdd(&g_acc[0], dsum);
}

// ---------------- positive-edge terms ---------------------------------------
__global__ void k_edges(const float* __restrict__ p,
                        const int* __restrict__ heads,
                        const int* __restrict__ tails, int E) {
    int tid = blockIdx.x * blockDim.x + threadIdx.x;
    int stride = gridDim.x * blockDim.x;
    float s1 = 0.0f, sp = 0.0f, se = 0.0f;
    for (int e = tid; e < E; e += stride) {
        int h = heads[e], tl = tails[e];
        float4 A = g_pts[h];
        float4 B = g_pts[tl];
        float dx = A.x - B.x;
        float dy = A.y - B.y;
        float d2 = fmaf(dx, dx, dy * dy);
        float pe = p[e];
        s1 = fmaf(pe, __logf(1.0f + d2), s1);  // p * log(1+d2) = -p*log(low_sim)
        sp += pe;
        se = fmaf(pe, __logf(pe), se);          // p * log(p)
    }
    double d1 = (double)s1, d2s = (double)sp, d3 = (double)se;
#pragma unroll
    for (int o = 16; o > 0; o >>= 1) {
        d1  += __shfl_down_sync(0xffffffffu, d1, o);
        d2s += __shfl_down_sync(0xffffffffu, d2s, o);
        d3  += __shfl_down_sync(0xffffffffu, d3, o);
    }
    if ((threadIdx.x & 31) == 0) {
        atomicAdd(&g_acc[1], d1);
        atomicAdd(&g_acc[2], d2s);
        atomicAdd(&g_acc[3], d3);
    }
}

// ---------------- final scalar assembly -------------------------------------
__global__ void k_final(float* out, int n) {
    double Z = g_acc[0] - (double)n;  // remove diagonal (each contributes 1)
    // loss = sum p*log(1+d2) + log(Z)*sum(p) + sum p*log(p)
    out[0] = (float)(g_acc[1] + log(Z) * g_acc[2] + g_acc[3]);
}

// ---------------- launch ------------------------------------------------------
extern "C" void kernel_launch(void* const* d_in, const int* in_sizes, int n_in,
                              void* d_out, int out_size) {
    const float2* emb = (const float2*)d_in[0];
    const float*  p     = (const float*)d_in[1];
    const int*    heads = (const int*)d_in[2];
    const int*    tails = (const int*)d_in[3];
    int n = in_sizes[0] / 2;
    int E = in_sizes[1];

    k_prep<<<(n + 255) / 256, 256>>>(emb, n);
    k_pair<<<NPAIR_BLOCKS, PAIR_THREADS>>>();
    k_edges<<<1536, 256>>>(p, heads, tails, E);
    k_final<<<1, 1>>>((float*)d_out, n);
}

// round 2
// speedup vs baseline: 1.1332x; 1.1332x over previous
#include <cuda_runtime.h>

// ---------------- problem constants ----------------
#define N_PTS 32768
#define TILE 2048
#define T_TILES (N_PTS / TILE)                      // 16
#define NPAIR_BLOCKS (T_TILES * (T_TILES + 1) / 2)  // 136
#define PAIR_THREADS 256
#define IB 8                                        // i-points per thread (256*8 = 2048)
#define NG (IB / 2)                                 // packed groups per thread
#define SCALE 3.5f

// ---------------- device scratch (no allocs allowed) ----------------
// g_pts[i] = { x*s, y*s, 1+sq, sq }
__device__ float4 g_pts[N_PTS];
// 0: Z_full (incl. diagonal), 1: sum p*log(1+d2), 2: sum p, 3: sum p*log(p)
__device__ double g_acc[4];

__device__ __forceinline__ float frcp(float x) {
    float r;
    asm("rcp.approx.ftz.f32 %0, %1;" : "=f"(r) : "f"(x));
    return r;
}

// ---- packed f32x2 helpers (Blackwell sm_103a) ----
typedef unsigned long long u64;

__device__ __forceinline__ u64 pack2(float lo, float hi) {
    u64 r;
    asm("mov.b64 %0, {%1, %2};" : "=l"(r) : "f"(lo), "f"(hi));
    return r;
}
__device__ __forceinline__ void unpack2(u64 v, float& lo, float& hi) {
    asm("mov.b64 {%0, %1}, %2;" : "=f"(lo), "=f"(hi) : "l"(v));
}
__device__ __forceinline__ u64 fma2(u64 a, u64 b, u64 c) {
    u64 d;
    asm("fma.rn.f32x2 %0, %1, %2, %3;" : "=l"(d) : "l"(a), "l"(b), "l"(c));
    return d;
}
__device__ __forceinline__ u64 add2(u64 a, u64 b) {
    u64 d;
    asm("add.rn.f32x2 %0, %1, %2;" : "=l"(d) : "l"(a), "l"(b));
    return d;
}

// ---------------- prep: scale points, precompute norms, zero accumulators ----
__global__ void k_prep(const float2* __restrict__ emb, int n) {
    int i = blockIdx.x * blockDim.x + threadIdx.x;
    if (i == 0) {
        g_acc[0] = 0.0; g_acc[1] = 0.0; g_acc[2] = 0.0; g_acc[3] = 0.0;
    }
    if (i < n) {
        float2 e = emb[i];
        float x = e.x * SCALE;
        float y = e.y * SCALE;
        float sq = fmaf(x, x, y * y);
        g_pts[i] = make_float4(x, y, 1.0f + sq, sq);
    }
}

// ---------------- pairwise partition sum over tile upper triangle -----------
// Each block computes a FULL TILE x TILE square of pair terms (diagonal tiles
// included once, off-diagonal tiles doubled by symmetry) => equal work/block.
__global__ void __launch_bounds__(PAIR_THREADS) k_pair() {
    // pre-broadcast j-tile values: sx[j]=(xj,xj), sy[j]=(yj,yj), sz[j]=(1+sqj,1+sqj)
    __shared__ u64 sx[TILE];
    __shared__ u64 sy[TILE];
    __shared__ u64 sz[TILE];

    int t = blockIdx.x;
    // invert lower-triangular linear index: t = r*(r+1)/2 + c, c <= r
    int r = (int)((sqrtf(8.0f * (float)t + 1.0f) - 1.0f) * 0.5f);
    while ((r + 1) * (r + 2) / 2 <= t) r++;
    while (r * (r + 1) / 2 > t) r--;
    int c = t - r * (r + 1) / 2;
    int bi = c, bj = r;  // bi <= bj

    int jbase = bj * TILE;
    int ibase = bi * TILE;

    for (int k = threadIdx.x; k < TILE; k += PAIR_THREADS) {
        float4 P = g_pts[jbase + k];
        sx[k] = pack2(P.x, P.x);
        sy[k] = pack2(P.y, P.y);
        sz[k] = pack2(P.z, P.z);
    }
    __syncthreads();

    // per-thread i-points: IB consecutive, packed in pairs
    u64 m2[NG], n2[NG], s2[NG];
    float acc[NG];
    int i0 = ibase + threadIdx.x * IB;
#pragma unroll
    for (int g = 0; g < NG; g++) {
        float4 A = g_pts[i0 + 2 * g];
        float4 B = g_pts[i0 + 2 * g + 1];
        m2[g] = pack2(-2.0f * A.x, -2.0f * B.x);
        n2[g] = pack2(-2.0f * A.y, -2.0f * B.y);
        s2[g] = pack2(A.w, B.w);  // sq_i
        acc[g] = 0.0f;
    }

#pragma unroll 4
    for (int j = 0; j < TILE; j++) {
        u64 Jx = sx[j], Jy = sy[j], Jz = sz[j];
#pragma unroll
        for (int g = 0; g < NG; g++) {
            u64 tt = fma2(n2[g], Jy, Jz);     // (1+sqj) - 2 yi yj
            tt = fma2(m2[g], Jx, tt);         //        - 2 xi xj
            u64 d2 = add2(tt, s2[g]);         // + sqi  => (a, b) = 1+dist2 pair
            float a, b;
            unpack2(d2, a, b);
            float prod = a * b;
            float ssum = a + b;
            acc[g] = fmaf(ssum, frcp(prod), acc[g]);  // 1/a + 1/b
        }
    }

    double dsum = 0.0;
#pragma unroll
    for (int g = 0; g < NG; g++) dsum += (double)acc[g];
    if (bi != bj) dsum *= 2.0;  // off-diagonal tiles counted twice by symmetry

#pragma unroll
    for (int o = 16; o > 0; o >>= 1)
        dsum += __shfl_down_sync(0xffffffffu, dsum, o);
    if ((threadIdx.x & 31) == 0)
        atomicAdd(&g_acc[0], dsum);
}

// ---------------- positive-edge terms ---------------------------------------
__global__ void k_edges(const float* __restrict__ p,
                        const int* __restrict__ heads,
                        const int* __restrict__ tails, int E) {
    int tid = blockIdx.x * blockDim.x + threadIdx.x;
    int stride = gridDim.x * blockDim.x;
    float s1 = 0.0f, sp = 0.0f, se = 0.0f;
    for (int e = tid; e < E; e += stride) {
        int h = heads[e], tl = tails[e];
        float4 A = g_pts[h];
        float4 B = g_pts[tl];
        float dx = A.x - B.x;
        float dy = A.y - B.y;
        float d2 = fmaf(dx, dx, dy * dy);
        float pe = p[e];
        s1 = fmaf(pe, __logf(1.0f + d2), s1);  // p * log(1+d2) = -p*log(low_sim)
        sp += pe;
        se = fmaf(pe, __logf(pe), se);          // p * log(p)
    }
    double d1 = (double)s1, d2s = (double)sp, d3 = (double)se;
#pragma unroll
    for (int o = 16; o > 0; o >>= 1) {
        d1  += __shfl_down_sync(0xffffffffu, d1, o);
        d2s += __shfl_down_sync(0xffffffffu, d2s, o);
        d3  += __shfl_down_sync(0xffffffffu, d3, o);
    }
    if ((threadIdx.x & 31) == 0) {
        atomicAdd(&g_acc[1], d1);
        atomicAdd(&g_acc[2], d2s);
        atomicAdd(&g_acc[3], d3);
    }
}

// ---------------- final scalar assembly -------------------------------------
__global__ void k_final(float* out, int n) {
    double Z = g_acc[0] - (double)n;  // remove diagonal (each contributes 1)
    // loss = sum p*log(1+d2) + log(Z)*sum(p) + sum p*log(p)
    out[0] = (float)(g_acc[1] + log(Z) * g_acc[2] + g_acc[3]);
}

// ---------------- launch ------------------------------------------------------
extern "C" void kernel_launch(void* const* d_in, const int* in_sizes, int n_in,
                              void* d_out, int out_size) {
    const float2* emb = (const float2*)d_in[0];
    const float*  p     = (const float*)d_in[1];
    const int*    heads = (const int*)d_in[2];
    const int*    tails = (const int*)d_in[3];
    int n = in_sizes[0] / 2;
    int E = in_sizes[1];

    k_prep<<<(n + 255) / 256, 256>>>(emb, n);
    k_pair<<<NPAIR_BLOCKS, PAIR_THREADS>>>();
    k_edges<<<1536, 256>>>(p, heads, tails, E);
    k_final<<<1, 1>>>((float*)d_out, n);
}

// round 3
// speedup vs baseline: 1.6268x; 1.4355x over previous
#include <cuda_runtime.h>

// ---------------- problem constants ----------------
#define N_PTS 32768
#define TILE 2048
#define T_TILES (N_PTS / TILE)                      // 16
#define NPAIR_BLOCKS (T_TILES * (T_TILES + 1) / 2)  // 136
#define PAIR_THREADS 512
#define IB 4                                        // i-points per thread (512*4 = 2048)
#define NG (IB / 2)                                 // packed i-groups per thread
#define EDGE_BLOCKS 512
#define EDGE_THREADS 256
#define SCALE 3.5f
#define SCALE2 12.25f

// ---------------- device scratch (no allocs allowed) ----------------
__device__ double g_part[NPAIR_BLOCKS];  // per-block pair sums
__device__ double g_e1[EDGE_BLOCKS];     // sum p*log(1+d2)
__device__ double g_e2[EDGE_BLOCKS];     // sum p
__device__ double g_e3[EDGE_BLOCKS];     // sum p*log(p)

typedef unsigned long long u64;

__device__ __forceinline__ float frcp(float x) {
    float r;
    asm("rcp.approx.ftz.f32 %0, %1;" : "=f"(r) : "f"(x));
    return r;
}
__device__ __forceinline__ u64 pack2(float lo, float hi) {
    u64 r;
    asm("mov.b64 %0, {%1, %2};" : "=l"(r) : "f"(lo), "f"(hi));
    return r;
}
__device__ __forceinline__ void unpack2(u64 v, float& lo, float& hi) {
    asm("mov.b64 {%0, %1}, %2;" : "=f"(lo), "=f"(hi) : "l"(v));
}
__device__ __forceinline__ u64 fma2(u64 a, u64 b, u64 c) {
    u64 d;
    asm("fma.rn.f32x2 %0, %1, %2, %3;" : "=l"(d) : "l"(a), "l"(b), "l"(c));
    return d;
}
__device__ __forceinline__ u64 add2(u64 a, u64 b) {
    u64 d;
    asm("add.rn.f32x2 %0, %1, %2;" : "=l"(d) : "l"(a), "l"(b));
    return d;
}
__device__ __forceinline__ u64 mul2(u64 a, u64 b) {
    u64 d;
    asm("mul.rn.f32x2 %0, %1, %2;" : "=l"(d) : "l"(a), "l"(b));
    return d;
}

// ---------------- pairwise partition sum over tile upper triangle -----------
// Each block computes a FULL TILE x TILE square (diagonal tiles once,
// off-diagonal doubled by symmetry) => equal work/block, no atomics.
__global__ void __launch_bounds__(PAIR_THREADS) k_pair(const float2* __restrict__ emb) {
    // j-tile, pre-broadcast packed: sx[j]=(xj,xj), sy[j]=(yj,yj), sz[j]=(1+sqj,1+sqj)
    __shared__ __align__(16) u64 sx[TILE];
    __shared__ __align__(16) u64 sy[TILE];
    __shared__ __align__(16) u64 sz[TILE];

    int t = blockIdx.x;
    // invert lower-triangular linear index: t = r*(r+1)/2 + c, c <= r
    int r = (int)((sqrtf(8.0f * (float)t + 1.0f) - 1.0f) * 0.5f);
    while ((r + 1) * (r + 2) / 2 <= t) r++;
    while (r * (r + 1) / 2 > t) r--;
    int c = t - r * (r + 1) / 2;
    int bi = c, bj = r;  // bi <= bj

    int jbase = bj * TILE;
    int ibase = bi * TILE;

    // cooperative j-tile load: scale + precompute, straight from emb
    for (int k = threadIdx.x; k < TILE; k += PAIR_THREADS) {
        float2 e = emb[jbase + k];
        float x = e.x * SCALE;
        float y = e.y * SCALE;
        float sq = fmaf(x, x, y * y);
        sx[k] = pack2(x, x);
        sy[k] = pack2(y, y);
        sz[k] = pack2(1.0f + sq, 1.0f + sq);
    }
    __syncthreads();

    // per-thread i-points: IB consecutive, packed 2 i's per register
    u64 m2[NG], n2[NG], s2[NG], acc2[NG];
    int i0 = ibase + threadIdx.x * IB;
#pragma unroll
    for (int g = 0; g < NG; g++) {
        float2 ea = emb[i0 + 2 * g];
        float2 eb = emb[i0 + 2 * g + 1];
        float xa = ea.x * SCALE, ya = ea.y * SCALE;
        float xb = eb.x * SCALE, yb = eb.y * SCALE;
        m2[g] = pack2(-2.0f * xa, -2.0f * xb);
        n2[g] = pack2(-2.0f * ya, -2.0f * yb);
        s2[g] = pack2(fmaf(xa, xa, ya * ya), fmaf(xb, xb, yb * yb));
        acc2[g] = pack2(0.0f, 0.0f);
    }

#pragma unroll 4
    for (int j = 0; j < TILE; j += 2) {
        ulonglong2 JX = *reinterpret_cast<const ulonglong2*>(&sx[j]);
        ulonglong2 JY = *reinterpret_cast<const ulonglong2*>(&sy[j]);
        ulonglong2 JZ = *reinterpret_cast<const ulonglong2*>(&sz[j]);
#pragma unroll
        for (int g = 0; g < NG; g++) {
            // denominators (1+d2) for (i0,i1) x (j, j+1): two packed values
            u64 d1 = fma2(m2[g], JX.x, fma2(n2[g], JY.x, add2(JZ.x, s2[g])));
            u64 d2 = fma2(m2[g], JX.y, fma2(n2[g], JY.y, add2(JZ.y, s2[g])));
            // 1/a + 1/b = (a+b) * rcp(a*b), done packed per i-lane across j-pair
            u64 pr = mul2(d1, d2);
            u64 sm = add2(d1, d2);
            float plo, phi;
            unpack2(pr, plo, phi);
            u64 r2 = pack2(frcp(plo), frcp(phi));
            acc2[g] = fma2(sm, r2, acc2[g]);
        }
    }

    double dsum = 0.0;
#pragma unroll
    for (int g = 0; g < NG; g++) {
        float lo, hi;
        unpack2(acc2[g], lo, hi);
        dsum += (double)lo + (double)hi;
    }
    if (bi != bj) dsum *= 2.0;  // off-diagonal tiles counted twice by symmetry

    // block reduction: warp shuffle then shared scratch (reuse sx)
#pragma unroll
    for (int o = 16; o > 0; o >>= 1)
        dsum += __shfl_down_sync(0xffffffffu, dsum, o);

    double* sred = reinterpret_cast<double*>(sx);
    __syncthreads();
    if ((threadIdx.x & 31) == 0)
        sred[threadIdx.x >> 5] = dsum;
    __syncthreads();
    if (threadIdx.x < 32) {
        double v = (threadIdx.x < (PAIR_THREADS / 32)) ? sred[threadIdx.x] : 0.0;
#pragma unroll
        for (int o = 8; o > 0; o >>= 1)
            v += __shfl_down_sync(0xffffffffu, v, o);
        if (threadIdx.x == 0)
            g_part[blockIdx.x] = v;
    }
}

// ---------------- positive-edge terms ---------------------------------------
__global__ void __launch_bounds__(EDGE_THREADS) k_edges(
        const float2* __restrict__ emb,
        const float* __restrict__ p,
        const int* __restrict__ heads,
        const int* __restrict__ tails, int E) {
    int tid = blockIdx.x * blockDim.x + threadIdx.x;
    int stride = gridDim.x * blockDim.x;
    float s1 = 0.0f, sp = 0.0f, se = 0.0f;
    for (int e = tid; e < E; e += stride) {
        int h = heads[e], tl = tails[e];
        float2 A = emb[h];
        float2 B = emb[tl];
        float dx = A.x - B.x;
        float dy = A.y - B.y;
        float d2 = SCALE2 * fmaf(dx, dx, dy * dy);
        float pe = p[e];
        s1 = fmaf(pe, __logf(1.0f + d2), s1);  // p * log(1+d2) = -p*log(low_sim)
        sp += pe;
        se = fmaf(pe, __logf(pe), se);          // p * log(p)
    }
    double d1 = (double)s1, d2s = (double)sp, d3 = (double)se;
#pragma unroll
    for (int o = 16; o > 0; o >>= 1) {
        d1  += __shfl_down_sync(0xffffffffu, d1, o);
        d2s += __shfl_down_sync(0xffffffffu, d2s, o);
        d3  += __shfl_down_sync(0xffffffffu, d3, o);
    }
    __shared__ double sh1[EDGE_THREADS / 32], sh2[EDGE_THREADS / 32], sh3[EDGE_THREADS / 32];
    if ((threadIdx.x & 31) == 0) {
        int w = threadIdx.x >> 5;
        sh1[w] = d1; sh2[w] = d2s; sh3[w] = d3;
    }
    __syncthreads();
    if (threadIdx.x < 32) {
        int nw = EDGE_THREADS / 32;
        double v1 = (threadIdx.x < nw) ? sh1[threadIdx.x] : 0.0;
        double v2 = (threadIdx.x < nw) ? sh2[threadIdx.x] : 0.0;
        double v3 = (threadIdx.x < nw) ? sh3[threadIdx.x] : 0.0;
#pragma unroll
        for (int o = 4; o > 0; o >>= 1) {
            v1 += __shfl_down_sync(0xffffffffu, v1, o);
            v2 += __shfl_down_sync(0xffffffffu, v2, o);
            v3 += __shfl_down_sync(0xffffffffu, v3, o);
        }
        if (threadIdx.x == 0) {
            g_e1[blockIdx.x] = v1;
            g_e2[blockIdx.x] = v2;
            g_e3[blockIdx.x] = v3;
        }
    }
}

// ---------------- final reduce + scalar assembly -----------------------------
__global__ void __launch_bounds__(256) k_final(float* out, int n) {
    double z = 0.0, e1 = 0.0, e2 = 0.0, e3 = 0.0;
    for (int i = threadIdx.x; i < NPAIR_BLOCKS; i += 256) z += g_part[i];
    for (int i = threadIdx.x; i < EDGE_BLOCKS; i += 256) {
        e1 += g_e1[i]; e2 += g_e2[i]; e3 += g_e3[i];
    }
#pragma unroll
    for (int o = 16; o > 0; o >>= 1) {
        z  += __shfl_down_sync(0xffffffffu, z, o);
        e1 += __shfl_down_sync(0xffffffffu, e1, o);
        e2 += __shfl_down_sync(0xffffffffu, e2, o);
        e3 += __shfl_down_sync(0xffffffffu, e3, o);
    }
    __shared__ double sz_[8], s1_[8], s2_[8], s3_[8];
    if ((threadIdx.x & 31) == 0) {
        int w = threadIdx.x >> 5;
        sz_[w] = z; s1_[w] = e1; s2_[w] = e2; s3_[w] = e3;
    }
    __syncthreads();
    if (threadIdx.x == 0) {
        double Z = 0.0, t1 = 0.0, t2 = 0.0, t3 = 0.0;
#pragma unroll
        for (int w = 0; w < 8; w++) {
            Z += sz_[w]; t1 += s1_[w]; t2 += s2_[w]; t3 += s3_[w];
        }
        Z -= (double)n;  // remove diagonal (each contributes exactly 1)
        // loss = sum p*log(1+d2) + log(Z)*sum(p) + sum p*log(p)
        out[0] = (float)(t1 + log(Z) * t2 + t3);
    }
}

// ---------------- launch ------------------------------------------------------
extern "C" void kernel_launch(void* const* d_in, const int* in_sizes, int n_in,
                              void* d_out, int out_size) {
    const float2* emb   = (const float2*)d_in[0];
    const float*  p     = (const float*)d_in[1];
    const int*    heads = (const int*)d_in[2];
    const int*    tails = (const int*)d_in[3];
    int n = in_sizes[0] / 2;
    int E = in_sizes[1];

    k_pair<<<NPAIR_BLOCKS, PAIR_THREADS>>>(emb);
    k_edges<<<EDGE_BLOCKS, EDGE_THREADS>>>(emb, p, heads, tails, E);
    k_final<<<1, 256>>>((float*)d_out, n);
}